// round 15
// baseline (speedup 1.0000x reference)
#include <cuda_runtime.h>
#include <cuda_bf16.h>
#include <cuda_fp16.h>
#include <math.h>
#include <stdint.h>

#define Bz 4
#define Tz 512
#define Cz 768
#define Hz 12
#define Lz 8
#define Vz 512
#define FFz (4*Cz)
#define HDz (Cz/Hz)
#define Mz (Bz*Tz)
#define EPSz 1e-5f

// ---------------- scratch ----------------
__device__ float  g_x [Mz*Cz];
__device__ __half g_h [Mz*Cz];
__device__ __half g_q [Mz*Cz];
__device__ __half g_k [Mz*Cz];
__device__ __half g_v [Mz*Cz];
__device__ __half g_y [Mz*Cz];
__device__ __half g_ff[Mz*FFz];
// transposed fp16 weights: [N][K]
__device__ __half g_wq[Lz*Cz*Cz];
__device__ __half g_wk[Lz*Cz*Cz];
__device__ __half g_wv[Lz*Cz*Cz];
__device__ __half g_wp[Lz*Cz*Cz];
__device__ __half g_w1[Lz*Cz*FFz];
__device__ __half g_w2[Lz*FFz*Cz];
__device__ __half g_wh[Vz*Cz];

// ---------------- warp reductions ----------------
__device__ __forceinline__ float warp_sum(float v){
    #pragma unroll
    for (int o = 16; o; o >>= 1) v += __shfl_xor_sync(0xffffffffu, v, o);
    return v;
}
__device__ __forceinline__ float warp_max(float v){
    #pragma unroll
    for (int o = 16; o; o >>= 1) v = fmaxf(v, __shfl_xor_sync(0xffffffffu, v, o));
    return v;
}

// ================= mma / ldmatrix / cp.async helpers =================
__device__ __forceinline__ void mma_f16(float* d, const uint32_t* a, const uint32_t* b){
    asm volatile(
        "mma.sync.aligned.m16n8k16.row.col.f32.f16.f16.f32 "
        "{%0,%1,%2,%3}, {%4,%5,%6,%7}, {%8,%9}, {%0,%1,%2,%3};\n"
        : "+f"(d[0]), "+f"(d[1]), "+f"(d[2]), "+f"(d[3])
        : "r"(a[0]), "r"(a[1]), "r"(a[2]), "r"(a[3]), "r"(b[0]), "r"(b[1]));
}
__device__ __forceinline__ void ldsm4(uint32_t* r, uint32_t addr){
    asm volatile("ldmatrix.sync.aligned.m8n8.x4.shared.b16 {%0,%1,%2,%3}, [%4];"
        : "=r"(r[0]), "=r"(r[1]), "=r"(r[2]), "=r"(r[3]) : "r"(addr));
}
__device__ __forceinline__ void ldsm4t(uint32_t* r, uint32_t addr){
    asm volatile("ldmatrix.sync.aligned.m8n8.x4.trans.shared.b16 {%0,%1,%2,%3}, [%4];"
        : "=r"(r[0]), "=r"(r[1]), "=r"(r[2]), "=r"(r[3]) : "r"(addr));
}
__device__ __forceinline__ void cp16(uint32_t dst, const void* src){
    asm volatile("cp.async.cg.shared.global [%0], [%1], 16;" :: "r"(dst), "l"(src));
}
__device__ __forceinline__ void cp_commit(){ asm volatile("cp.async.commit_group;"); }
template<int N> __device__ __forceinline__ void cp_wait(){ asm volatile("cp.async.wait_group %0;" :: "n"(N)); }
__device__ __forceinline__ uint32_t h2u(__half2 h){ return *(uint32_t*)&h; }

// ---------------- embeddings ----------------
__global__ void embed_k(const int* __restrict__ idx, const float* __restrict__ tok,
                        const float* __restrict__ typ, const float* __restrict__ pos,
                        float* __restrict__ x){
    int i = blockIdx.x * blockDim.x + threadIdx.x;
    if (i >= Mz*Cz) return;
    int c = i % Cz;
    int bt = i / Cz;
    int t = bt % Tz;
    x[i] = tok[(size_t)idx[bt]*Cz + c] + pos[(size_t)t*Cz + c] + typ[Cz + c];
}

// ---------------- merged weight prep ----------------
struct WTArgs {
    const float* src[7];
    __half*      dst[7];
};
#define WT_BLOCKS (18432 + 18432 + 18432 + 384)

__global__ void wtrans_all_k(WTArgs a){
    int id = blockIdx.x;
    if (id >= 55296) {
        int t = threadIdx.y*32 + threadIdx.x;
        int base = (id - 55296)*1024 + t;
        #pragma unroll
        for (int i = 0; i < 4; i++) {
            int e = base + i*256;
            a.dst[6][e] = __float2half_rn(a.src[6][e]);
        }
        return;
    }
    int seg, K, N, lid;
    if (id < 18432)      { seg = id / 4608;  lid = id % 4608;  K = Cz;  N = Cz;  }
    else if (id < 36864) { seg = 4;          lid = id - 18432; K = Cz;  N = FFz; }
    else                 { seg = 5;          lid = id - 36864; K = FFz; N = Cz;  }
    const int tpl   = (K/32)*(N/32);
    const int layer = lid / tpl;
    const int t2    = lid % tpl;
    const int n0    = (t2 % (N/32)) * 32;
    const int k0    = (t2 / (N/32)) * 32;
    const float* src = a.src[seg] + (size_t)layer*K*N;
    __half*      dst = a.dst[seg] + (size_t)layer*K*N;
    __shared__ float tile[32][33];
    #pragma unroll
    for (int i = threadIdx.y; i < 32; i += 8)
        tile[i][threadIdx.x] = src[(size_t)(k0+i)*N + n0 + threadIdx.x];
    __syncthreads();
    #pragma unroll
    for (int i = threadIdx.y; i < 32; i += 8)
        dst[(size_t)(n0+i)*K + k0 + threadIdx.x] = __float2half_rn(tile[threadIdx.x][i]);
}

// ---------------- layernorm ----------------
template<int MODE>   // 0: fp32 out, 1: half out, 2: both
__global__ void ln_k(const float* __restrict__ in, const float* __restrict__ w,
                     const float* __restrict__ b, float* __restrict__ outf,
                     __half* __restrict__ outh){
    int row = blockIdx.x*8 + (threadIdx.x >> 5);
    int lane = threadIdx.x & 31;
    const float* xr = in + (size_t)row * Cz;
    float2 v[12];
    float s = 0.f, s2 = 0.f;
    #pragma unroll
    for (int i = 0; i < 12; i++) {
        float2 t = *(const float2*)&xr[2*lane + 64*i];
        v[i] = t; s += t.x + t.y; s2 += t.x*t.x + t.y*t.y;
    }
    s  = warp_sum(s);
    s2 = warp_sum(s2);
    float mean = s * (1.0f/Cz);
    float inv  = rsqrtf(s2 * (1.0f/Cz) - mean*mean + EPSz);
    #pragma unroll
    for (int i = 0; i < 12; i++) {
        int c = 2*lane + 64*i;
        float o0 = (v[i].x - mean) * inv * w[c]   + b[c];
        float o1 = (v[i].y - mean) * inv * w[c+1] + b[c+1];
        if (MODE != 1)
            *(float2*)(outf + (size_t)row*Cz + c) = make_float2(o0, o1);
        if (MODE != 0)
            *(__half2*)(outh + (size_t)row*Cz + c) = __floats2half2_rn(o0, o1);
    }
}

// ===== FP16 GEMM: BM64 BN64 BK64, 6-stage ring, TWO k-tiles per barrier, 2 CTAs/SM =====
#define GBM 64
#define GBN 64
#define GBK 64
#define GSTAGE (64*64)                       // halfs per stage tile (8 KB)
#define GSTG 6
#define GEMM_SMEM (GSTG*2*GSTAGE*2)          // 96 KB

extern __shared__ unsigned char smem_raw[];

template<bool GELU, bool OUTHALF>
__device__ __forceinline__ void gemm_body(
    const __half* __restrict__ A, const __half* __restrict__ Bt,
    const float* __restrict__ bias, const float* __restrict__ res,
    void* __restrict__ Cm, int Ndim, int Kdim, int m0, int n0)
{
    __half* As = (__half*)smem_raw;          // 6 x [64][64]
    __half* Bs = As + GSTG*GSTAGE;           // 6 x [64][64]

    const int tid  = threadIdx.x;
    const int lane = tid & 31;
    const int w    = tid >> 5;
    const int wm   = w >> 2;      // 0..1 (32 rows)
    const int wn   = w & 3;       // 0..3 (16 cols)
    const int gr   = lane >> 2;
    const int gc   = lane & 3;

    uint32_t as_base = (uint32_t)__cvta_generic_to_shared(As);
    uint32_t bs_base = (uint32_t)__cvta_generic_to_shared(Bs);

    const int srow = tid >> 2;          // 0..63
    const int sg0  = (tid & 3) * 2;     // 0,2,4,6
    uint32_t sdst[2];
    #pragma unroll
    for (int j = 0; j < 2; j++)
        sdst[j] = (uint32_t)(srow*8 + ((sg0+j) ^ (srow & 7))) * 16u;

    const int nk = Kdim / GBK;          // always even here (12 or 48)
    const int np = nk >> 1;

    #define ISSUE(T) do { \
        int _s = (T) % GSTG; int _k0 = (T) * GBK; \
        uint32_t _ab = as_base + (uint32_t)(_s*GSTAGE*2); \
        uint32_t _bb = bs_base + (uint32_t)(_s*GSTAGE*2); \
        const __half* _arow = &A[(size_t)(m0 + srow)*Kdim + _k0]; \
        const __half* _brow = &Bt[(size_t)(n0 + srow)*Kdim + _k0]; \
        cp16(_ab + sdst[0], _arow + (sg0+0)*8); \
        cp16(_ab + sdst[1], _arow + (sg0+1)*8); \
        cp16(_bb + sdst[0], _brow + (sg0+0)*8); \
        cp16(_bb + sdst[1], _brow + (sg0+1)*8); \
    } while(0)

    const int a_ghi = lane >> 4;                  // 0/1
    const int b_g   = lane >> 3;                  // 0..3
    int a_m[2], asw[2];
    #pragma unroll
    for (int mt = 0; mt < 2; mt++) {
        a_m[mt] = wm*32 + mt*16 + (lane & 15);
        asw[mt] = a_m[mt] & 7;
    }
    int b_n[2], bsw[2];
    #pragma unroll
    for (int nt = 0; nt < 2; nt++) {
        b_n[nt] = wn*16 + nt*8 + (lane & 7);
        bsw[nt] = b_n[nt] & 7;
    }

    float acc[2][2][4];
    #pragma unroll
    for (int i = 0; i < 2; i++)
        #pragma unroll
        for (int j = 0; j < 2; j++)
            #pragma unroll
            for (int q = 0; q < 4; q++) acc[i][j][q] = 0.f;

    // prologue: two pairs in flight
    ISSUE(0); ISSUE(1); cp_commit();    // pair 0 -> stages 0,1
    ISSUE(2); ISSUE(3); cp_commit();    // pair 1 -> stages 2,3

    for (int u = 0; u < np; u++) {
        cp_wait<1>();        // pair u arrived
        __syncthreads();     // everyone done reading pair u-1's predecessor stages
        if (u + 2 < np) { ISSUE(2*u + 4); ISSUE(2*u + 5); }
        cp_commit();
        #pragma unroll
        for (int half = 0; half < 2; half++) {
            const int t = 2*u + half;
            const uint32_t ab = as_base + (uint32_t)((t % GSTG)*GSTAGE*2);
            const uint32_t bb = bs_base + (uint32_t)((t % GSTG)*GSTAGE*2);

            uint32_t breg[2][8];
            #pragma unroll
            for (int nt = 0; nt < 2; nt++) {
                ldsm4(&breg[nt][0], bb + (uint32_t)(b_n[nt]*8 + ( b_g      ^ bsw[nt]))*16u);
                ldsm4(&breg[nt][4], bb + (uint32_t)(b_n[nt]*8 + ((b_g + 4) ^ bsw[nt]))*16u);
            }
            #pragma unroll
            for (int ks = 0; ks < 4; ks++) {
                uint32_t areg[2][4];
                #pragma unroll
                for (int mt = 0; mt < 2; mt++)
                    ldsm4(areg[mt], ab + (uint32_t)(a_m[mt]*8 + ((ks*2 + a_ghi) ^ asw[mt]))*16u);
                #pragma unroll
                for (int mt = 0; mt < 2; mt++)
                    #pragma unroll
                    for (int nt = 0; nt < 2; nt++)
                        mma_f16(acc[mt][nt], areg[mt], &breg[nt][ks*2]);
            }
        }
    }
    #undef ISSUE

    #pragma unroll
    for (int mt = 0; mt < 2; mt++) {
        #pragma unroll
        for (int nt = 0; nt < 2; nt++) {
            const int r0 = m0 + wm*32 + mt*16 + gr;
            const int c0 = n0 + wn*16 + nt*8 + gc*2;
            #pragma unroll
            for (int half = 0; half < 2; half++) {
                const int r = r0 + half*8;
                float v0 = acc[mt][nt][half*2 + 0];
                float v1 = acc[mt][nt][half*2 + 1];
                if (bias) { v0 += bias[c0]; v1 += bias[c0+1]; }
                if (GELU) {
                    v0 = 0.5f * v0 * (1.0f + erff(v0 * 0.70710678118654752f));
                    v1 = 0.5f * v1 * (1.0f + erff(v1 * 0.70710678118654752f));
                }
                if (res) {
                    v0 += res[(size_t)r*Ndim + c0];
                    v1 += res[(size_t)r*Ndim + c0 + 1];
                }
                if (OUTHALF)
                    *(__half2*)((__half*)Cm + (size_t)r*Ndim + c0) = __floats2half2_rn(v0, v1);
                else
                    *(float2*)((float*)Cm + (size_t)r*Ndim + c0) = make_float2(v0, v1);
            }
        }
    }
}

template<bool GELU, bool OUTHALF>
__global__ void __launch_bounds__(256, 2)
gemm_f16_k(const __half* __restrict__ A, const __half* __restrict__ Bt,
           const float* __restrict__ bias, const float* __restrict__ res,
           void* __restrict__ Cm, int Ndim, int Kdim){
    gemm_body<GELU, OUTHALF>(A, Bt, bias, res, Cm, Ndim, Kdim,
                             blockIdx.y*GBM, blockIdx.x*GBN);
}

__global__ void __launch_bounds__(256, 2)
qkv_k(const __half* __restrict__ h,
      const __half* __restrict__ Wq, const __half* __restrict__ Wk, const __half* __restrict__ Wv,
      const float* __restrict__ bq, const float* __restrict__ bk, const float* __restrict__ bv,
      __half* __restrict__ q, __half* __restrict__ k, __half* __restrict__ v){
    const __half* W  = (blockIdx.z == 0) ? Wq : (blockIdx.z == 1) ? Wk : Wv;
    const float*  bb = (blockIdx.z == 0) ? bq : (blockIdx.z == 1) ? bk : bv;
    __half*       o  = (blockIdx.z == 0) ? q  : (blockIdx.z == 1) ? k  : v;
    gemm_body<false, true>(h, W, bb, nullptr, o, Cz, Cz,
                           blockIdx.y*GBM, blockIdx.x*GBN);
}

// ============ fused attention fp16: 32 q-rows/CTA (R14: Q hoist + P double buffer) ============
#define SST 516
#define ATTF_SMEM (32*SST*4 + 3*32*64*2 + 3*64*64*2)

__global__ void __launch_bounds__(256, 2)
attn_fused_k(const __half* __restrict__ q, const __half* __restrict__ k,
             const __half* __restrict__ v, float* __restrict__ att,
             __half* __restrict__ y){
    float*  S  = (float*)smem_raw;             // [32][SST]
    __half* Qs = (__half*)(S + 32*SST);        // [32][64] swizzled (Q)
    __half* Ks = Qs + 3*32*64;                 // 3 x [64][64] swizzled (K, then V)

    const int qb = gridDim.x - 1 - blockIdx.x;
    const int q0 = qb * 32;
    const int bh = blockIdx.y;
    const int b = bh / Hz, h = bh % Hz;
    const int tid  = threadIdx.x;
    const int lane = tid & 31;
    const int w    = tid >> 5;
    const int wm   = w >> 2;
    const int wn   = w & 3;
    const int gr   = lane >> 2;
    const int gc   = lane & 3;
    const int ntiles = (qb >> 1) + 1;

    uint32_t qs_base = (uint32_t)__cvta_generic_to_shared(Qs);
    uint32_t ks_base = (uint32_t)__cvta_generic_to_shared(Ks);
    const uint32_t pb_base0 = qs_base + 32*64*2;
    const uint32_t pb_base1 = qs_base + 2*32*64*2;

    const int krow = tid >> 2;
    const int kg0  = (tid & 3) * 2;
    uint32_t kst[2];
    #pragma unroll
    for (int j = 0; j < 2; j++)
        kst[j] = (uint32_t)(krow*8 + ((kg0+j) ^ (krow & 7))) * 16u;
    const int qrow = tid >> 3;
    const int qg   = tid & 7;
    const uint32_t qst = (uint32_t)(qrow*8 + (qg ^ (qrow & 7))) * 16u;

    #define ISSUE_KT(T) do { \
        uint32_t _kb = ks_base + (uint32_t)(((T) % 3) * 8192); \
        const __half* _kp = &k[((size_t)(b*Tz + (T)*64 + krow))*Cz + h*HDz]; \
        cp16(_kb + kst[0], _kp + (kg0+0)*8); \
        cp16(_kb + kst[1], _kp + (kg0+1)*8); \
    } while(0)
    #define ISSUE_VT(T) do { \
        uint32_t _kb = ks_base + (uint32_t)(((T) % 3) * 8192); \
        const __half* _vp = &v[((size_t)(b*Tz + (T)*64 + krow))*Cz + h*HDz]; \
        cp16(_kb + kst[0], _vp + (kg0+0)*8); \
        cp16(_kb + kst[1], _vp + (kg0+1)*8); \
    } while(0)

    cp16(qs_base + qst, &q[((size_t)(b*Tz + q0 + qrow))*Cz + h*HDz + qg*8]);
    ISSUE_KT(0);
    cp_commit();
    if (ntiles > 1) ISSUE_KT(1);
    cp_commit();

    const int a_ghi = lane >> 4;
    const int b_g   = lane >> 3;
    const int am    = wm*16 + (lane & 15);
    const int asw   = am & 7;
    int b_n[2]; int bsw[2];
    #pragma unroll
    for (int nt = 0; nt < 2; nt++) {
        b_n[nt] = wn*16 + nt*8 + (lane & 7);
        bsw[nt] = b_n[nt] & 7;
    }

    // -------- phase 1: S = QK^T * scale (Q frags hoisted) --------
    uint32_t qfrag[4][4];
    for (int t = 0; t < ntiles; t++) {
        cp_wait<1>();
        __syncthreads();
        if (t == 0) {
            #pragma unroll
            for (int ks = 0; ks < 4; ks++)
                ldsm4(qfrag[ks], qs_base + (uint32_t)(am*8 + ((ks*2 + a_ghi) ^ asw))*16u);
        }
        if (t + 2 < ntiles) ISSUE_KT(t + 2);
        cp_commit();
        const uint32_t kb = ks_base + (uint32_t)((t % 3) * 8192);

        uint32_t breg[2][8];
        #pragma unroll
        for (int nt = 0; nt < 2; nt++) {
            ldsm4(&breg[nt][0], kb + (uint32_t)(b_n[nt]*8 + ( b_g      ^ bsw[nt]))*16u);
            ldsm4(&breg[nt][4], kb + (uint32_t)(b_n[nt]*8 + ((b_g + 4) ^ bsw[nt]))*16u);
        }
        float acc[2][4] = {};
        #pragma unroll
        for (int ks = 0; ks < 4; ks++) {
            mma_f16(acc[0], qfrag[ks], &breg[0][ks*2]);
            mma_f16(acc[1], qfrag[ks], &breg[1][ks*2]);
        }
        const int kt0 = t * 64;
        #pragma unroll
        for (int nt = 0; nt < 2; nt++) {
            const int r = wm*16 + gr;
            const int c = kt0 + wn*16 + nt*8 + gc*2;
            *(float2*)&S[ r     *SST + c] = make_float2(acc[nt][0]*0.125f, acc[nt][1]*0.125f);
            *(float2*)&S[(r + 8)*SST + c] = make_float2(acc[nt][2]*0.125f, acc[nt][3]*0.125f);
        }
    }
    __syncthreads();

    // -------- softmax (warp per row) --------
    const int kmax = ntiles * 64;
    for (int r = w; r < 32; r += 8) {
        const int qt = q0 + r;
        float* Sr = &S[r*SST];
        float mx = -3.0e38f;
        for (int kt = lane; kt < kmax; kt += 32) {
            float s = Sr[kt];
            if (kt <= qt) mx = fmaxf(mx, s);
        }
        mx = warp_max(mx);
        float sum = 0.f;
        for (int kt = lane; kt < kmax; kt += 32) {
            float e = (kt <= qt) ? __expf(Sr[kt] - mx) : 0.f;
            Sr[kt] = e;
            sum += e;
        }
        sum = warp_sum(sum);
        const float inv = 1.0f / sum;
        float* orow = att + ((size_t)bh*Tz + qt)*Tz;
        for (int kt = lane; kt < kmax; kt += 32) {
            float p = Sr[kt] * inv;
            Sr[kt] = p;
            orow[kt] = p;
        }
        for (int kt = kmax + lane; kt < Tz; kt += 32) orow[kt] = 0.f;
    }
    __syncthreads();

    // -------- phase 2: y = P @ V, P double-buffered --------
    const int pr = tid & 31;
    const int pg = tid >> 5;
    const uint32_t pst = (uint32_t)(pr*8 + (pg ^ (pr & 7))) * 16u;

    #define CONV_P(T, PB) do { \
        const float* _sp = &S[pr*SST + (T)*64 + pg*8]; \
        uint4 _val; \
        _val.x = h2u(__floats2half2_rn(_sp[0], _sp[1])); \
        _val.y = h2u(__floats2half2_rn(_sp[2], _sp[3])); \
        _val.z = h2u(__floats2half2_rn(_sp[4], _sp[5])); \
        _val.w = h2u(__floats2half2_rn(_sp[6], _sp[7])); \
        *(uint4*)((char*)Qs + ((PB) ? 2*32*64*2 : 32*64*2) + pst) = _val; \
    } while(0)

    CONV_P(0, 0);
    ISSUE_VT(0); cp_commit();
    if (ntiles > 1) { ISSUE_VT(1); } cp_commit();

    float acc2[2][4] = {};

    for (int t = 0; t < ntiles; t++) {
        cp_wait<1>();
        __syncthreads();
        if (t + 2 < ntiles) ISSUE_VT(t + 2);
        cp_commit();
        if (t + 1 < ntiles) CONV_P(t + 1, (t + 1) & 1);
        const uint32_t vb = ks_base + (uint32_t)((t % 3) * 8192);
        const uint32_t pb = (t & 1) ? pb_base1 : pb_base0;

        uint32_t breg[2][8];
        #pragma unroll
        for (int nt = 0; nt < 2; nt++) {
            const int dgr = wn*2 + nt;
            const int r0 = lane;
            const int r1 = 32 + lane;
            ldsm4t(&breg[nt][0], vb + (uint32_t)(r0*8 + (dgr ^ (r0 & 7)))*16u);
            ldsm4t(&breg[nt][4], vb + (uint32_t)(r1*8 + (dgr ^ (r1 & 7)))*16u);
        }
        #pragma unroll
        for (int ks = 0; ks < 4; ks++) {
            uint32_t areg[4];
            ldsm4(areg, pb + (uint32_t)(am*8 + ((ks*2 + a_ghi) ^ asw))*16u);
            mma_f16(acc2[0], areg, &breg[0][ks*2]);
            mma_f16(acc2[1], areg, &breg[1][ks*2]);
        }
    }
    #undef CONV_P

    __half* Cp = (__half*)y + ((size_t)(b*Tz + q0))*Cz + h*HDz;
    #pragma unroll
    for (int nt = 0; nt < 2; nt++) {
        const int r = wm*16 + gr;
        const int c = wn*16 + nt*8 + gc*2;
        *(__half2*)&Cp[(size_t) r     *Cz + c] = __floats2half2_rn(acc2[nt][0], acc2[nt][1]);
        *(__half2*)&Cp[(size_t)(r + 8)*Cz + c] = __floats2half2_rn(acc2[nt][2], acc2[nt][3]);
    }
    #undef ISSUE_KT
    #undef ISSUE_VT
}

// ---------------- host launch ----------------
extern "C" void kernel_launch(void* const* d_in, const int* in_sizes, int n_in,
                              void* d_out, int out_size){
    const int*   idx    = (const int*)  d_in[0];
    const float* tok    = (const float*)d_in[1];
    const float* typ    = (const float*)d_in[2];
    const float* pos    = (const float*)d_in[3];
    const float* Wq     = (const float*)d_in[4];
    const float* bq     = (const float*)d_in[5];
    const float* Wk     = (const float*)d_in[6];
    const float* bk     = (const float*)d_in[7];
    const float* Wv     = (const float*)d_in[8];
    const float* bv     = (const float*)d_in[9];
    const float* Wp     = (const float*)d_in[10];
    const float* bp     = (const float*)d_in[11];
    const float* ln1_w  = (const float*)d_in[12];
    const float* ln1_b  = (const float*)d_in[13];
    const float* ln2_w  = (const float*)d_in[14];
    const float* ln2_b  = (const float*)d_in[15];
    const float* W1     = (const float*)d_in[16];
    const float* b1     = (const float*)d_in[17];
    const float* W2     = (const float*)d_in[18];
    const float* b2     = (const float*)d_in[19];
    const float* lnf_w  = (const float*)d_in[20];
    const float* lnf_b  = (const float*)d_in[21];
    const float* head_w = (const float*)d_in[22];

    float* out        = (float*)d_out;
    float* out_logits = out;
    float* out_x      = out + (size_t)Mz*Vz;
    float* out_att    = out_x + (size_t)Mz*Cz;

    float  *px;
    __half *ph, *pq, *pk, *pv, *py, *pff;
    __half *pwq, *pwk, *pwv, *pwp, *pw1, *pw2, *pwh;
    cudaGetSymbolAddress((void**)&px,  g_x);
    cudaGetSymbolAddress((void**)&ph,  g_h);
    cudaGetSymbolAddress((void**)&pq,  g_q);
    cudaGetSymbolAddress((void**)&pk,  g_k);
    cudaGetSymbolAddress((void**)&pv,  g_v);
    cudaGetSymbolAddress((void**)&py,  g_y);
    cudaGetSymbolAddress((void**)&pff, g_ff);
    cudaGetSymbolAddress((void**)&pwq, g_wq);
    cudaGetSymbolAddress((void**)&pwk, g_wk);
    cudaGetSymbolAddress((void**)&pwv, g_wv);
    cudaGetSymbolAddress((void**)&pwp, g_wp);
    cudaGetSymbolAddress((void**)&pw1, g_w1);
    cudaGetSymbolAddress((void**)&pw2, g_w2);
    cudaGetSymbolAddress((void**)&pwh, g_wh);

    static bool attrs_set = false;
    if (!attrs_set) {
        cudaFuncSetAttribute((const void*)gemm_f16_k<false,false>, cudaFuncAttributeMaxDynamicSharedMemorySize, GEMM_SMEM);
        cudaFuncSetAttribute((const void*)gemm_f16_k<true,true>,   cudaFuncAttributeMaxDynamicSharedMemorySize, GEMM_SMEM);
        cudaFuncSetAttribute((const void*)qkv_k,                   cudaFuncAttributeMaxDynamicSharedMemorySize, GEMM_SMEM);
        cudaFuncSetAttribute((const void*)attn_fused_k,            cudaFuncAttributeMaxDynamicSharedMemorySize, ATTF_SMEM);
        attrs_set = true;
    }

    WTArgs wt;
    wt.src[0]=Wq;  wt.dst[0]=pwq;
    wt.src[1]=Wk;  wt.dst[1]=pwk;
    wt.src[2]=Wv;  wt.dst[2]=pwv;
    wt.src[3]=Wp;  wt.dst[3]=pwp;
    wt.src[4]=W1;  wt.dst[4]=pw1;
    wt.src[5]=W2;  wt.dst[5]=pw2;
    wt.src[6]=head_w; wt.dst[6]=pwh;
    wtrans_all_k<<<WT_BLOCKS, dim3(32,8)>>>(wt);

    embed_k<<<(Mz*Cz + 255)/256, 256>>>(idx, tok, typ, pos, px);

    dim3 gQKV3(Cz/GBN, Mz/GBM, 3);   // 12 x 32 x 3
    dim3 gP(Cz/GBN,  Mz/GBM);        // 12 x 32
    dim3 gFF1(FFz/GBN, Mz/GBM);      // 48 x 32
    dim3 gHead(Vz/GBN, Mz/GBM);      // 8 x 32
    dim3 gAtt(Tz/32, Bz*Hz);         // 16 x 48

    for (int l = 0; l < Lz; l++) {
        float* attL = out_att + (size_t)l*Bz*Hz*Tz*Tz;

        ln_k<1><<<Mz/8, 256>>>(px, ln1_w + (size_t)l*Cz, ln1_b + (size_t)l*Cz, nullptr, ph);
        qkv_k<<<gQKV3, 256, GEMM_SMEM>>>(ph,
            pwq + (size_t)l*Cz*Cz, pwk + (size_t)l*Cz*Cz, pwv + (size_t)l*Cz*Cz,
            bq + (size_t)l*Cz, bk + (size_t)l*Cz, bv + (size_t)l*Cz,
            pq, pk, pv);
        attn_fused_k<<<gAtt, 256, ATTF_SMEM>>>(pq, pk, pv, attL, py);
        gemm_f16_k<false,false><<<gP, 256, GEMM_SMEM>>>(py, pwp + (size_t)l*Cz*Cz,
            bp + (size_t)l*Cz, px, px, Cz, Cz);
        ln_k<1><<<Mz/8, 256>>>(px, ln2_w + (size_t)l*Cz, ln2_b + (size_t)l*Cz, nullptr, ph);
        gemm_f16_k<true,true><<<gFF1, 256, GEMM_SMEM>>>(ph, pw1 + (size_t)l*Cz*FFz,
            b1 + (size_t)l*FFz, nullptr, pff, FFz, Cz);
        gemm_f16_k<false,false><<<gP, 256, GEMM_SMEM>>>(pff, pw2 + (size_t)l*FFz*Cz,
            b2 + (size_t)l*Cz, px, px, Cz, FFz);
    }

    ln_k<2><<<Mz/8, 256>>>(px, lnf_w, lnf_b, out_x, ph);
    gemm_f16_k<false,false><<<gHead, 256, GEMM_SMEM>>>(ph, pwh, nullptr, nullptr,
                                                       out_logits, Vz, Cz);
}

// round 16
// speedup vs baseline: 1.0609x; 1.0609x over previous
#include <cuda_runtime.h>
#include <cuda_bf16.h>
#include <cuda_fp16.h>
#include <math.h>
#include <stdint.h>

#define Bz 4
#define Tz 512
#define Cz 768
#define Hz 12
#define Lz 8
#define Vz 512
#define FFz (4*Cz)
#define HDz (Cz/Hz)
#define Mz (Bz*Tz)
#define EPSz 1e-5f

// ---------------- scratch ----------------
__device__ float  g_x [Mz*Cz];
__device__ __half g_h [Mz*Cz];
__device__ __half g_q [Mz*Cz];
__device__ __half g_k [Mz*Cz];
__device__ __half g_v [Mz*Cz];
__device__ __half g_y [Mz*Cz];
__device__ __half g_ff[Mz*FFz];
// transposed fp16 weights: [N][K]
__device__ __half g_wq[Lz*Cz*Cz];
__device__ __half g_wk[Lz*Cz*Cz];
__device__ __half g_wv[Lz*Cz*Cz];
__device__ __half g_wp[Lz*Cz*Cz];
__device__ __half g_w1[Lz*Cz*FFz];
__device__ __half g_w2[Lz*FFz*Cz];
__device__ __half g_wh[Vz*Cz];

// ---------------- warp reductions ----------------
__device__ __forceinline__ float warp_sum(float v){
    #pragma unroll
    for (int o = 16; o; o >>= 1) v += __shfl_xor_sync(0xffffffffu, v, o);
    return v;
}
__device__ __forceinline__ float warp_max(float v){
    #pragma unroll
    for (int o = 16; o; o >>= 1) v = fmaxf(v, __shfl_xor_sync(0xffffffffu, v, o));
    return v;
}

// ================= mma / ldmatrix / cp.async helpers =================
__device__ __forceinline__ void mma_f16(float* d, const uint32_t* a, const uint32_t* b){
    asm volatile(
        "mma.sync.aligned.m16n8k16.row.col.f32.f16.f16.f32 "
        "{%0,%1,%2,%3}, {%4,%5,%6,%7}, {%8,%9}, {%0,%1,%2,%3};\n"
        : "+f"(d[0]), "+f"(d[1]), "+f"(d[2]), "+f"(d[3])
        : "r"(a[0]), "r"(a[1]), "r"(a[2]), "r"(a[3]), "r"(b[0]), "r"(b[1]));
}
__device__ __forceinline__ void ldsm4(uint32_t* r, uint32_t addr){
    asm volatile("ldmatrix.sync.aligned.m8n8.x4.shared.b16 {%0,%1,%2,%3}, [%4];"
        : "=r"(r[0]), "=r"(r[1]), "=r"(r[2]), "=r"(r[3]) : "r"(addr));
}
__device__ __forceinline__ void ldsm4t(uint32_t* r, uint32_t addr){
    asm volatile("ldmatrix.sync.aligned.m8n8.x4.trans.shared.b16 {%0,%1,%2,%3}, [%4];"
        : "=r"(r[0]), "=r"(r[1]), "=r"(r[2]), "=r"(r[3]) : "r"(addr));
}
__device__ __forceinline__ void cp16(uint32_t dst, const void* src){
    asm volatile("cp.async.cg.shared.global [%0], [%1], 16;" :: "r"(dst), "l"(src));
}
__device__ __forceinline__ void cp_commit(){ asm volatile("cp.async.commit_group;"); }
template<int N> __device__ __forceinline__ void cp_wait(){ asm volatile("cp.async.wait_group %0;" :: "n"(N)); }
__device__ __forceinline__ uint32_t h2u(__half2 h){ return *(uint32_t*)&h; }

// ---------------- embeddings ----------------
__global__ void embed_k(const int* __restrict__ idx, const float* __restrict__ tok,
                        const float* __restrict__ typ, const float* __restrict__ pos,
                        float* __restrict__ x){
    int i = blockIdx.x * blockDim.x + threadIdx.x;
    if (i >= Mz*Cz) return;
    int c = i % Cz;
    int bt = i / Cz;
    int t = bt % Tz;
    x[i] = tok[(size_t)idx[bt]*Cz + c] + pos[(size_t)t*Cz + c] + typ[Cz + c];
}

// ---------------- merged weight prep ----------------
struct WTArgs {
    const float* src[7];
    __half*      dst[7];
};
#define WT_BLOCKS (18432 + 18432 + 18432 + 384)

__global__ void wtrans_all_k(WTArgs a){
    int id = blockIdx.x;
    if (id >= 55296) {
        int t = threadIdx.y*32 + threadIdx.x;
        int base = (id - 55296)*1024 + t;
        #pragma unroll
        for (int i = 0; i < 4; i++) {
            int e = base + i*256;
            a.dst[6][e] = __float2half_rn(a.src[6][e]);
        }
        return;
    }
    int seg, K, N, lid;
    if (id < 18432)      { seg = id / 4608;  lid = id % 4608;  K = Cz;  N = Cz;  }
    else if (id < 36864) { seg = 4;          lid = id - 18432; K = Cz;  N = FFz; }
    else                 { seg = 5;          lid = id - 36864; K = FFz; N = Cz;  }
    const int tpl   = (K/32)*(N/32);
    const int layer = lid / tpl;
    const int t2    = lid % tpl;
    const int n0    = (t2 % (N/32)) * 32;
    const int k0    = (t2 / (N/32)) * 32;
    const float* src = a.src[seg] + (size_t)layer*K*N;
    __half*      dst = a.dst[seg] + (size_t)layer*K*N;
    __shared__ float tile[32][33];
    #pragma unroll
    for (int i = threadIdx.y; i < 32; i += 8)
        tile[i][threadIdx.x] = src[(size_t)(k0+i)*N + n0 + threadIdx.x];
    __syncthreads();
    #pragma unroll
    for (int i = threadIdx.y; i < 32; i += 8)
        dst[(size_t)(n0+i)*K + k0 + threadIdx.x] = __float2half_rn(tile[threadIdx.x][i]);
}

// ---------------- layernorm ----------------
template<int MODE>   // 0: fp32 out, 1: half out, 2: both
__global__ void ln_k(const float* __restrict__ in, const float* __restrict__ w,
                     const float* __restrict__ b, float* __restrict__ outf,
                     __half* __restrict__ outh){
    int row = blockIdx.x*8 + (threadIdx.x >> 5);
    int lane = threadIdx.x & 31;
    const float* xr = in + (size_t)row * Cz;
    float2 v[12];
    float s = 0.f, s2 = 0.f;
    #pragma unroll
    for (int i = 0; i < 12; i++) {
        float2 t = *(const float2*)&xr[2*lane + 64*i];
        v[i] = t; s += t.x + t.y; s2 += t.x*t.x + t.y*t.y;
    }
    s  = warp_sum(s);
    s2 = warp_sum(s2);
    float mean = s * (1.0f/Cz);
    float inv  = rsqrtf(s2 * (1.0f/Cz) - mean*mean + EPSz);
    #pragma unroll
    for (int i = 0; i < 12; i++) {
        int c = 2*lane + 64*i;
        float o0 = (v[i].x - mean) * inv * w[c]   + b[c];
        float o1 = (v[i].y - mean) * inv * w[c+1] + b[c+1];
        if (MODE != 1)
            *(float2*)(outf + (size_t)row*Cz + c) = make_float2(o0, o1);
        if (MODE != 0)
            *(__half2*)(outh + (size_t)row*Cz + c) = __floats2half2_rn(o0, o1);
    }
}

// ===== FP16 tensor-core GEMM: BM64 BN64 BK64, 3-stage, 4 CTAs/SM (48 KB smem) =====
#define GBM 64
#define GBN 64
#define GBK 64
#define GSTAGE (64*64)                       // halfs per stage tile (8 KB)
#define GSTG 3
#define GEMM_SMEM (GSTG*2*GSTAGE*2)          // 48 KB

extern __shared__ unsigned char smem_raw[];

template<bool GELU, bool OUTHALF>
__device__ __forceinline__ void gemm_body(
    const __half* __restrict__ A, const __half* __restrict__ Bt,
    const float* __restrict__ bias, const float* __restrict__ res,
    void* __restrict__ Cm, int Ndim, int Kdim, int m0, int n0)
{
    __half* As = (__half*)smem_raw;          // 3 x [64][64]
    __half* Bs = As + GSTG*GSTAGE;           // 3 x [64][64]

    const int tid  = threadIdx.x;
    const int lane = tid & 31;
    const int w    = tid >> 5;
    const int wm   = w >> 2;      // 0..1 (32 rows)
    const int wn   = w & 3;       // 0..3 (16 cols)
    const int gr   = lane >> 2;
    const int gc   = lane & 3;

    uint32_t as_base = (uint32_t)__cvta_generic_to_shared(As);
    uint32_t bs_base = (uint32_t)__cvta_generic_to_shared(Bs);

    const int srow = tid >> 2;          // 0..63
    const int sg0  = (tid & 3) * 2;     // 0,2,4,6
    uint32_t sdst[2];
    #pragma unroll
    for (int j = 0; j < 2; j++)
        sdst[j] = (uint32_t)(srow*8 + ((sg0+j) ^ (srow & 7))) * 16u;

    const int nk = Kdim / GBK;

    #define ISSUE(T) do { \
        int _s = (T) % GSTG; int _k0 = (T) * GBK; \
        uint32_t _ab = as_base + (uint32_t)(_s*GSTAGE*2); \
        uint32_t _bb = bs_base + (uint32_t)(_s*GSTAGE*2); \
        const __half* _arow = &A[(size_t)(m0 + srow)*Kdim + _k0]; \
        const __half* _brow = &Bt[(size_t)(n0 + srow)*Kdim + _k0]; \
        cp16(_ab + sdst[0], _arow + (sg0+0)*8); \
        cp16(_ab + sdst[1], _arow + (sg0+1)*8); \
        cp16(_bb + sdst[0], _brow + (sg0+0)*8); \
        cp16(_bb + sdst[1], _brow + (sg0+1)*8); \
    } while(0)

    const int a_ghi = lane >> 4;                  // 0/1
    const int b_g   = lane >> 3;                  // 0..3
    int a_m[2], asw[2];
    #pragma unroll
    for (int mt = 0; mt < 2; mt++) {
        a_m[mt] = wm*32 + mt*16 + (lane & 15);
        asw[mt] = a_m[mt] & 7;
    }
    int b_n[2], bsw[2];
    #pragma unroll
    for (int nt = 0; nt < 2; nt++) {
        b_n[nt] = wn*16 + nt*8 + (lane & 7);
        bsw[nt] = b_n[nt] & 7;
    }

    float acc[2][2][4];
    #pragma unroll
    for (int i = 0; i < 2; i++)
        #pragma unroll
        for (int j = 0; j < 2; j++)
            #pragma unroll
            for (int q = 0; q < 4; q++) acc[i][j][q] = 0.f;

    ISSUE(0); cp_commit();
    ISSUE(1); cp_commit();

    for (int t = 0; t < nk; t++) {
        cp_wait<1>();
        __syncthreads();
        if (t + 2 < nk) ISSUE(t + 2);
        cp_commit();
        const uint32_t ab = as_base + (uint32_t)((t % GSTG)*GSTAGE*2);
        const uint32_t bb = bs_base + (uint32_t)((t % GSTG)*GSTAGE*2);

        uint32_t breg[2][8];
        #pragma unroll
        for (int nt = 0; nt < 2; nt++) {
            ldsm4(&breg[nt][0], bb + (uint32_t)(b_n[nt]*8 + ( b_g      ^ bsw[nt]))*16u);
            ldsm4(&breg[nt][4], bb + (uint32_t)(b_n[nt]*8 + ((b_g + 4) ^ bsw[nt]))*16u);
        }
        #pragma unroll
        for (int ks = 0; ks < 4; ks++) {
            uint32_t areg[2][4];
            #pragma unroll
            for (int mt = 0; mt < 2; mt++)
                ldsm4(areg[mt], ab + (uint32_t)(a_m[mt]*8 + ((ks*2 + a_ghi) ^ asw[mt]))*16u);
            #pragma unroll
            for (int mt = 0; mt < 2; mt++)
                #pragma unroll
                for (int nt = 0; nt < 2; nt++)
                    mma_f16(acc[mt][nt], areg[mt], &breg[nt][ks*2]);
        }
    }
    #undef ISSUE

    #pragma unroll
    for (int mt = 0; mt < 2; mt++) {
        #pragma unroll
        for (int nt = 0; nt < 2; nt++) {
            const int r0 = m0 + wm*32 + mt*16 + gr;
            const int c0 = n0 + wn*16 + nt*8 + gc*2;
            #pragma unroll
            for (int half = 0; half < 2; half++) {
                const int r = r0 + half*8;
                float v0 = acc[mt][nt][half*2 + 0];
                float v1 = acc[mt][nt][half*2 + 1];
                if (bias) { v0 += bias[c0]; v1 += bias[c0+1]; }
                if (GELU) {
                    v0 = 0.5f * v0 * (1.0f + erff(v0 * 0.70710678118654752f));
                    v1 = 0.5f * v1 * (1.0f + erff(v1 * 0.70710678118654752f));
                }
                if (res) {
                    v0 += res[(size_t)r*Ndim + c0];
                    v1 += res[(size_t)r*Ndim + c0 + 1];
                }
                if (OUTHALF)
                    *(__half2*)((__half*)Cm + (size_t)r*Ndim + c0) = __floats2half2_rn(v0, v1);
                else
                    *(float2*)((float*)Cm + (size_t)r*Ndim + c0) = make_float2(v0, v1);
            }
        }
    }
}

template<bool GELU, bool OUTHALF>
__global__ void __launch_bounds__(256, 4)
gemm_f16_k(const __half* __restrict__ A, const __half* __restrict__ Bt,
           const float* __restrict__ bias, const float* __restrict__ res,
           void* __restrict__ Cm, int Ndim, int Kdim){
    gemm_body<GELU, OUTHALF>(A, Bt, bias, res, Cm, Ndim, Kdim,
                             blockIdx.y*GBM, blockIdx.x*GBN);
}

__global__ void __launch_bounds__(256, 4)
qkv_k(const __half* __restrict__ h,
      const __half* __restrict__ Wq, const __half* __restrict__ Wk, const __half* __restrict__ Wv,
      const float* __restrict__ bq, const float* __restrict__ bk, const float* __restrict__ bv,
      __half* __restrict__ q, __half* __restrict__ k, __half* __restrict__ v){
    const __half* W  = (blockIdx.z == 0) ? Wq : (blockIdx.z == 1) ? Wk : Wv;
    const float*  bb = (blockIdx.z == 0) ? bq : (blockIdx.z == 1) ? bk : bv;
    __half*       o  = (blockIdx.z == 0) ? q  : (blockIdx.z == 1) ? k  : v;
    gemm_body<false, true>(h, W, bb, nullptr, o, Cz, Cz,
                           blockIdx.y*GBM, blockIdx.x*GBN);
}

// ============ fused attention fp16: 32 q-rows/CTA (R14: Q hoist + P double buffer) ============
#define SST 516
#define ATTF_SMEM (32*SST*4 + 3*32*64*2 + 3*64*64*2)

__global__ void __launch_bounds__(256, 2)
attn_fused_k(const __half* __restrict__ q, const __half* __restrict__ k,
             const __half* __restrict__ v, float* __restrict__ att,
             __half* __restrict__ y){
    float*  S  = (float*)smem_raw;             // [32][SST]
    __half* Qs = (__half*)(S + 32*SST);        // [32][64] swizzled (Q)
    __half* Ks = Qs + 3*32*64;                 // 3 x [64][64] swizzled (K, then V)

    const int qb = gridDim.x - 1 - blockIdx.x;
    const int q0 = qb * 32;
    const int bh = blockIdx.y;
    const int b = bh / Hz, h = bh % Hz;
    const int tid  = threadIdx.x;
    const int lane = tid & 31;
    const int w    = tid >> 5;
    const int wm   = w >> 2;
    const int wn   = w & 3;
    const int gr   = lane >> 2;
    const int gc   = lane & 3;
    const int ntiles = (qb >> 1) + 1;

    uint32_t qs_base = (uint32_t)__cvta_generic_to_shared(Qs);
    uint32_t ks_base = (uint32_t)__cvta_generic_to_shared(Ks);
    const uint32_t pb_base0 = qs_base + 32*64*2;
    const uint32_t pb_base1 = qs_base + 2*32*64*2;

    const int krow = tid >> 2;
    const int kg0  = (tid & 3) * 2;
    uint32_t kst[2];
    #pragma unroll
    for (int j = 0; j < 2; j++)
        kst[j] = (uint32_t)(krow*8 + ((kg0+j) ^ (krow & 7))) * 16u;
    const int qrow = tid >> 3;
    const int qg   = tid & 7;
    const uint32_t qst = (uint32_t)(qrow*8 + (qg ^ (qrow & 7))) * 16u;

    #define ISSUE_KT(T) do { \
        uint32_t _kb = ks_base + (uint32_t)(((T) % 3) * 8192); \
        const __half* _kp = &k[((size_t)(b*Tz + (T)*64 + krow))*Cz + h*HDz]; \
        cp16(_kb + kst[0], _kp + (kg0+0)*8); \
        cp16(_kb + kst[1], _kp + (kg0+1)*8); \
    } while(0)
    #define ISSUE_VT(T) do { \
        uint32_t _kb = ks_base + (uint32_t)(((T) % 3) * 8192); \
        const __half* _vp = &v[((size_t)(b*Tz + (T)*64 + krow))*Cz + h*HDz]; \
        cp16(_kb + kst[0], _vp + (kg0+0)*8); \
        cp16(_kb + kst[1], _vp + (kg0+1)*8); \
    } while(0)

    cp16(qs_base + qst, &q[((size_t)(b*Tz + q0 + qrow))*Cz + h*HDz + qg*8]);
    ISSUE_KT(0);
    cp_commit();
    if (ntiles > 1) ISSUE_KT(1);
    cp_commit();

    const int a_ghi = lane >> 4;
    const int b_g   = lane >> 3;
    const int am    = wm*16 + (lane & 15);
    const int asw   = am & 7;
    int b_n[2]; int bsw[2];
    #pragma unroll
    for (int nt = 0; nt < 2; nt++) {
        b_n[nt] = wn*16 + nt*8 + (lane & 7);
        bsw[nt] = b_n[nt] & 7;
    }

    // -------- phase 1: S = QK^T * scale (Q frags hoisted) --------
    uint32_t qfrag[4][4];
    for (int t = 0; t < ntiles; t++) {
        cp_wait<1>();
        __syncthreads();
        if (t == 0) {
            #pragma unroll
            for (int ks = 0; ks < 4; ks++)
                ldsm4(qfrag[ks], qs_base + (uint32_t)(am*8 + ((ks*2 + a_ghi) ^ asw))*16u);
        }
        if (t + 2 < ntiles) ISSUE_KT(t + 2);
        cp_commit();
        const uint32_t kb = ks_base + (uint32_t)((t % 3) * 8192);

        uint32_t breg[2][8];
        #pragma unroll
        for (int nt = 0; nt < 2; nt++) {
            ldsm4(&breg[nt][0], kb + (uint32_t)(b_n[nt]*8 + ( b_g      ^ bsw[nt]))*16u);
            ldsm4(&breg[nt][4], kb + (uint32_t)(b_n[nt]*8 + ((b_g + 4) ^ bsw[nt]))*16u);
        }
        float acc[2][4] = {};
        #pragma unroll
        for (int ks = 0; ks < 4; ks++) {
            mma_f16(acc[0], qfrag[ks], &breg[0][ks*2]);
            mma_f16(acc[1], qfrag[ks], &breg[1][ks*2]);
        }
        const int kt0 = t * 64;
        #pragma unroll
        for (int nt = 0; nt < 2; nt++) {
            const int r = wm*16 + gr;
            const int c = kt0 + wn*16 + nt*8 + gc*2;
            *(float2*)&S[ r     *SST + c] = make_float2(acc[nt][0]*0.125f, acc[nt][1]*0.125f);
            *(float2*)&S[(r + 8)*SST + c] = make_float2(acc[nt][2]*0.125f, acc[nt][3]*0.125f);
        }
    }
    __syncthreads();

    // -------- softmax (warp per row) --------
    const int kmax = ntiles * 64;
    for (int r = w; r < 32; r += 8) {
        const int qt = q0 + r;
        float* Sr = &S[r*SST];
        float mx = -3.0e38f;
        for (int kt = lane; kt < kmax; kt += 32) {
            float s = Sr[kt];
            if (kt <= qt) mx = fmaxf(mx, s);
        }
        mx = warp_max(mx);
        float sum = 0.f;
        for (int kt = lane; kt < kmax; kt += 32) {
            float e = (kt <= qt) ? __expf(Sr[kt] - mx) : 0.f;
            Sr[kt] = e;
            sum += e;
        }
        sum = warp_sum(sum);
        const float inv = 1.0f / sum;
        float* orow = att + ((size_t)bh*Tz + qt)*Tz;
        for (int kt = lane; kt < kmax; kt += 32) {
            float p = Sr[kt] * inv;
            Sr[kt] = p;
            orow[kt] = p;
        }
        for (int kt = kmax + lane; kt < Tz; kt += 32) orow[kt] = 0.f;
    }
    __syncthreads();

    // -------- phase 2: y = P @ V, P double-buffered --------
    const int pr = tid & 31;
    const int pg = tid >> 5;
    const uint32_t pst = (uint32_t)(pr*8 + (pg ^ (pr & 7))) * 16u;

    #define CONV_P(T, PB) do { \
        const float* _sp = &S[pr*SST + (T)*64 + pg*8]; \
        uint4 _val; \
        _val.x = h2u(__floats2half2_rn(_sp[0], _sp[1])); \
        _val.y = h2u(__floats2half2_rn(_sp[2], _sp[3])); \
        _val.z = h2u(__floats2half2_rn(_sp[4], _sp[5])); \
        _val.w = h2u(__floats2half2_rn(_sp[6], _sp[7])); \
        *(uint4*)((char*)Qs + ((PB) ? 2*32*64*2 : 32*64*2) + pst) = _val; \
    } while(0)

    CONV_P(0, 0);
    ISSUE_VT(0); cp_commit();
    if (ntiles > 1) { ISSUE_VT(1); } cp_commit();

    float acc2[2][4] = {};

    for (int t = 0; t < ntiles; t++) {
        cp_wait<1>();
        __syncthreads();
        if (t + 2 < ntiles) ISSUE_VT(t + 2);
        cp_commit();
        if (t + 1 < ntiles) CONV_P(t + 1, (t + 1) & 1);
        const uint32_t vb = ks_base + (uint32_t)((t % 3) * 8192);
        const uint32_t pb = (t & 1) ? pb_base1 : pb_base0;

        uint32_t breg[2][8];
        #pragma unroll
        for (int nt = 0; nt < 2; nt++) {
            const int dgr = wn*2 + nt;
            const int r0 = lane;
            const int r1 = 32 + lane;
            ldsm4t(&breg[nt][0], vb + (uint32_t)(r0*8 + (dgr ^ (r0 & 7)))*16u);
            ldsm4t(&breg[nt][4], vb + (uint32_t)(r1*8 + (dgr ^ (r1 & 7)))*16u);
        }
        #pragma unroll
        for (int ks = 0; ks < 4; ks++) {
            uint32_t areg[4];
            ldsm4(areg, pb + (uint32_t)(am*8 + ((ks*2 + a_ghi) ^ asw))*16u);
            mma_f16(acc2[0], areg, &breg[0][ks*2]);
            mma_f16(acc2[1], areg, &breg[1][ks*2]);
        }
    }
    #undef CONV_P

    __half* Cp = (__half*)y + ((size_t)(b*Tz + q0))*Cz + h*HDz;
    #pragma unroll
    for (int nt = 0; nt < 2; nt++) {
        const int r = wm*16 + gr;
        const int c = wn*16 + nt*8 + gc*2;
        *(__half2*)&Cp[(size_t) r     *Cz + c] = __floats2half2_rn(acc2[nt][0], acc2[nt][1]);
        *(__half2*)&Cp[(size_t)(r + 8)*Cz + c] = __floats2half2_rn(acc2[nt][2], acc2[nt][3]);
    }
    #undef ISSUE_KT
    #undef ISSUE_VT
}

// ---------------- host launch ----------------
extern "C" void kernel_launch(void* const* d_in, const int* in_sizes, int n_in,
                              void* d_out, int out_size){
    const int*   idx    = (const int*)  d_in[0];
    const float* tok    = (const float*)d_in[1];
    const float* typ    = (const float*)d_in[2];
    const float* pos    = (const float*)d_in[3];
    const float* Wq     = (const float*)d_in[4];
    const float* bq     = (const float*)d_in[5];
    const float* Wk     = (const float*)d_in[6];
    const float* bk     = (const float*)d_in[7];
    const float* Wv     = (const float*)d_in[8];
    const float* bv     = (const float*)d_in[9];
    const float* Wp     = (const float*)d_in[10];
    const float* bp     = (const float*)d_in[11];
    const float* ln1_w  = (const float*)d_in[12];
    const float* ln1_b  = (const float*)d_in[13];
    const float* ln2_w  = (const float*)d_in[14];
    const float* ln2_b  = (const float*)d_in[15];
    const float* W1     = (const float*)d_in[16];
    const float* b1     = (const float*)d_in[17];
    const float* W2     = (const float*)d_in[18];
    const float* b2     = (const float*)d_in[19];
    const float* lnf_w  = (const float*)d_in[20];
    const float* lnf_b  = (const float*)d_in[21];
    const float* head_w = (const float*)d_in[22];

    float* out        = (float*)d_out;
    float* out_logits = out;
    float* out_x      = out + (size_t)Mz*Vz;
    float* out_att    = out_x + (size_t)Mz*Cz;

    float  *px;
    __half *ph, *pq, *pk, *pv, *py, *pff;
    __half *pwq, *pwk, *pwv, *pwp, *pw1, *pw2, *pwh;
    cudaGetSymbolAddress((void**)&px,  g_x);
    cudaGetSymbolAddress((void**)&ph,  g_h);
    cudaGetSymbolAddress((void**)&pq,  g_q);
    cudaGetSymbolAddress((void**)&pk,  g_k);
    cudaGetSymbolAddress((void**)&pv,  g_v);
    cudaGetSymbolAddress((void**)&py,  g_y);
    cudaGetSymbolAddress((void**)&pff, g_ff);
    cudaGetSymbolAddress((void**)&pwq, g_wq);
    cudaGetSymbolAddress((void**)&pwk, g_wk);
    cudaGetSymbolAddress((void**)&pwv, g_wv);
    cudaGetSymbolAddress((void**)&pwp, g_wp);
    cudaGetSymbolAddress((void**)&pw1, g_w1);
    cudaGetSymbolAddress((void**)&pw2, g_w2);
    cudaGetSymbolAddress((void**)&pwh, g_wh);

    static bool attrs_set = false;
    if (!attrs_set) {
        cudaFuncSetAttribute((const void*)gemm_f16_k<false,false>, cudaFuncAttributeMaxDynamicSharedMemorySize, GEMM_SMEM);
        cudaFuncSetAttribute((const void*)gemm_f16_k<true,true>,   cudaFuncAttributeMaxDynamicSharedMemorySize, GEMM_SMEM);
        cudaFuncSetAttribute((const void*)qkv_k,                   cudaFuncAttributeMaxDynamicSharedMemorySize, GEMM_SMEM);
        cudaFuncSetAttribute((const void*)attn_fused_k,            cudaFuncAttributeMaxDynamicSharedMemorySize, ATTF_SMEM);
        attrs_set = true;
    }

    WTArgs wt;
    wt.src[0]=Wq;  wt.dst[0]=pwq;
    wt.src[1]=Wk;  wt.dst[1]=pwk;
    wt.src[2]=Wv;  wt.dst[2]=pwv;
    wt.src[3]=Wp;  wt.dst[3]=pwp;
    wt.src[4]=W1;  wt.dst[4]=pw1;
    wt.src[5]=W2;  wt.dst[5]=pw2;
    wt.src[6]=head_w; wt.dst[6]=pwh;
    wtrans_all_k<<<WT_BLOCKS, dim3(32,8)>>>(wt);

    embed_k<<<(Mz*Cz + 255)/256, 256>>>(idx, tok, typ, pos, px);

    dim3 gQKV3(Cz/GBN, Mz/GBM, 3);   // 12 x 32 x 3
    dim3 gP(Cz/GBN,  Mz/GBM);        // 12 x 32
    dim3 gFF1(FFz/GBN, Mz/GBM);      // 48 x 32
    dim3 gHead(Vz/GBN, Mz/GBM);      // 8 x 32
    dim3 gAtt(Tz/32, Bz*Hz);         // 16 x 48

    for (int l = 0; l < Lz; l++) {
        float* attL = out_att + (size_t)l*Bz*Hz*Tz*Tz;

        ln_k<1><<<Mz/8, 256>>>(px, ln1_w + (size_t)l*Cz, ln1_b + (size_t)l*Cz, nullptr, ph);
        qkv_k<<<gQKV3, 256, GEMM_SMEM>>>(ph,
            pwq + (size_t)l*Cz*Cz, pwk + (size_t)l*Cz*Cz, pwv + (size_t)l*Cz*Cz,
            bq + (size_t)l*Cz, bk + (size_t)l*Cz, bv + (size_t)l*Cz,
            pq, pk, pv);
        attn_fused_k<<<gAtt, 256, ATTF_SMEM>>>(pq, pk, pv, attL, py);
        gemm_f16_k<false,false><<<gP, 256, GEMM_SMEM>>>(py, pwp + (size_t)l*Cz*Cz,
            bp + (size_t)l*Cz, px, px, Cz, Cz);
        ln_k<1><<<Mz/8, 256>>>(px, ln2_w + (size_t)l*Cz, ln2_b + (size_t)l*Cz, nullptr, ph);
        gemm_f16_k<true,true><<<gFF1, 256, GEMM_SMEM>>>(ph, pw1 + (size_t)l*Cz*FFz,
            b1 + (size_t)l*FFz, nullptr, pff, FFz, Cz);
        gemm_f16_k<false,false><<<gP, 256, GEMM_SMEM>>>(pff, pw2 + (size_t)l*FFz*Cz,
            b2 + (size_t)l*Cz, px, px, Cz, FFz);
    }

    ln_k<2><<<Mz/8, 256>>>(px, lnf_w, lnf_b, out_x, ph);
    gemm_f16_k<false,false><<<gHead, 256, GEMM_SMEM>>>(ph, pwh, nullptr, nullptr,
                                                       out_logits, Vz, Cz);
}